// round 11
// baseline (speedup 1.0000x reference)
#include <cuda_runtime.h>
#include <math.h>
#include <stdint.h>

#define BB 64
#define TT 512
#define DD 256
#define HSZ 256
#define G4 1024
#define HS2 512

typedef unsigned long long ull;

// ---------------- device scratch (static: no allocation) ----------------
__device__ float g_XW[(size_t)TT * BB * G4];  // [t][b][gatecol]  128MB
__device__ float g_preH[BB * HSZ];
__device__ float g_preC[BB * HSZ];
__device__ float g_h[BB * HSZ];
__device__ unsigned g_bar[8];

// output offsets (floats)
#define OFF_HSEQ ((size_t)0)
#define OFF_CSEQ ((size_t)8388608)
#define OFF_HMU  ((size_t)16777216)
#define OFF_HSTD ((size_t)25165824)
#define OFF_CMU  ((size_t)33554432)
#define OFF_CSTD ((size_t)41943040)
#define OFF_HT   ((size_t)50331648)
#define OFF_CT   ((size_t)50348032)

// ---------------- f32x2 helpers ----------------
__device__ __forceinline__ void f2fma(ull& d, ull a, ull b) {
    asm("fma.rn.f32x2 %0, %1, %2, %0;" : "+l"(d) : "l"(a), "l"(b));
}
__device__ __forceinline__ float f2sum(ull v) {
    float lo, hi;
    asm("mov.b64 {%0,%1}, %2;" : "=f"(lo), "=f"(hi) : "l"(v));
    return lo + hi;
}
__device__ __forceinline__ ull f2pack(float lo, float hi) {
    ull v;
    asm("mov.b64 %0, {%1,%2};" : "=l"(v) : "f"(lo), "f"(hi));
    return v;
}
__device__ __forceinline__ void ld16cg(const float* p, ull& lo, ull& hi) {
    asm volatile("ld.global.cg.v2.b64 {%0,%1}, [%2];" : "=l"(lo), "=l"(hi) : "l"(p));
}

__global__ void bar_reset_kernel() {
    if (threadIdx.x < 8) g_bar[threadIdx.x] = 0u;
}

// ---------------- precompute: XW[t][b][col] = x[b][t][:] @ W_ih + bias ----------------
#define XSP_STRIDE 140
#define WSP_STRIDE 132

__global__ __launch_bounds__(256) void xw_kernel(const float* __restrict__ x,
                                                 const float* __restrict__ wih,
                                                 const float* __restrict__ bias) {
    __shared__ float XsP[32 * XSP_STRIDE];  // [k2][t*2+par]
    __shared__ float WsP[32 * WSP_STRIDE];  // [k2][col*2+par]
    const int bx = blockIdx.x;      // 0..15  col block (64 cols)
    const int by = blockIdx.y;      // 0..7   t block (64 t)
    const int bz = blockIdx.z;      // 0..63  b
    const int tid = threadIdx.x;
    const int tx = tid & 15;        // col quad
    const int ty = tid >> 4;        // t quad

    ull acc[4][4];
#pragma unroll
    for (int i = 0; i < 4; i++)
#pragma unroll
        for (int j = 0; j < 4; j++) acc[i][j] = 0ull;

    for (int kc = 0; kc < 4; kc++) {
        const int k0 = kc * 64;
        __syncthreads();
        for (int i = tid; i < 4096; i += 256) {
            int kk = i >> 6, cc = i & 63;
            WsP[(kk >> 1) * WSP_STRIDE + cc * 2 + (kk & 1)] =
                wih[(size_t)(k0 + kk) * G4 + bx * 64 + cc];
        }
        for (int i = tid; i < 4096; i += 256) {
            int tt2 = i >> 6, kk = i & 63;
            XsP[(kk >> 1) * XSP_STRIDE + tt2 * 2 + (kk & 1)] =
                x[((size_t)bz * TT + by * 64 + tt2) * DD + k0 + kk];
        }
        __syncthreads();
#pragma unroll 8
        for (int kk2 = 0; kk2 < 32; kk2++) {
            const float* XP = &XsP[kk2 * XSP_STRIDE + ty * 8];
            const float* WP = &WsP[kk2 * WSP_STRIDE + tx * 8];
            ulonglong2 aA = *(const ulonglong2*)XP;
            ulonglong2 aB = *(const ulonglong2*)(XP + 4);
            ulonglong2 wA = *(const ulonglong2*)WP;
            ulonglong2 wB = *(const ulonglong2*)(WP + 4);
            f2fma(acc[0][0], aA.x, wA.x); f2fma(acc[0][1], aA.x, wA.y);
            f2fma(acc[0][2], aA.x, wB.x); f2fma(acc[0][3], aA.x, wB.y);
            f2fma(acc[1][0], aA.y, wA.x); f2fma(acc[1][1], aA.y, wA.y);
            f2fma(acc[1][2], aA.y, wB.x); f2fma(acc[1][3], aA.y, wB.y);
            f2fma(acc[2][0], aB.x, wA.x); f2fma(acc[2][1], aB.x, wA.y);
            f2fma(acc[2][2], aB.x, wB.x); f2fma(acc[2][3], aB.x, wB.y);
            f2fma(acc[3][0], aB.y, wA.x); f2fma(acc[3][1], aB.y, wA.y);
            f2fma(acc[3][2], aB.y, wB.x); f2fma(acc[3][3], aB.y, wB.y);
        }
    }
    const int col0 = bx * 64 + tx * 4;
    const float4 bv = *(const float4*)&bias[col0];
#pragma unroll
    for (int i = 0; i < 4; i++) {
        int t = by * 64 + ty * 4 + i;
        float4 v;
        v.x = f2sum(acc[i][0]) + bv.x;
        v.y = f2sum(acc[i][1]) + bv.y;
        v.z = f2sum(acc[i][2]) + bv.z;
        v.w = f2sum(acc[i][3]) + bv.w;
        *(float4*)&g_XW[((size_t)t * BB + bz) * G4 + col0] = v;
    }
}

// ---------------- fast nonlinearities ----------------
__device__ __forceinline__ float ftanh_(float x) {
    float e = __expf(-2.f * fabsf(x));
    float t = __fdividef(1.f - e, 1.f + e);
    return copysignf(t, x);
}
__device__ __forceinline__ float fsig_(float x) {
    return fmaf(0.5f, ftanh_(0.5f * x), 0.5f);
}

__device__ __forceinline__ void rg_barrier(unsigned* bar, unsigned target) {
    __syncthreads();
    if (threadIdx.x == 0) {
        asm volatile("red.release.gpu.add.u32 [%0], 1;" :: "l"(bar) : "memory");
        unsigned v;
        do {
            asm volatile("ld.acquire.gpu.u32 %0, [%1];" : "=r"(v) : "l"(bar) : "memory");
        } while (v < target);
    }
    __syncthreads();
}

__device__ __forceinline__ void cl_barrier() {
    asm volatile("barrier.cluster.arrive.release.aligned;" ::: "memory");
    asm volatile("barrier.cluster.wait.acquire.aligned;" ::: "memory");
}

// ---------------- persistent recurrent kernel ----------------
// 8 rowgroups x 16 CTAs (one cluster each when available).
// All 8 warps compute both phases; k split 8 ways (32 k per warp).
#define PP 66   // Part pitch (floats)

__global__ __launch_bounds__(256, 1) void lstm_kernel(const float* __restrict__ whh,
                                                      const float* __restrict__ hrep,
                                                      const float* __restrict__ crep,
                                                      const float* __restrict__ eps_h,
                                                      const float* __restrict__ eps_c,
                                                      float* __restrict__ out,
                                                      int use_cluster) {
    __shared__ __align__(16) float Part[64 * PP];  // [(r*8+ks)][64 cols]
    __shared__ float Cs[128];                      // c state, CTA-local [r*16+j]

    const int tid = threadIdx.x;
    const int rg = blockIdx.x >> 4;       // row group: rows rg*8 .. rg*8+7
    const int cb = blockIdx.x & 15;       // col block (== cluster rank)
    unsigned* bar = &g_bar[rg];
    const int w = tid >> 5, lane = tid & 31;
    const int ks = w;                     // k-slice: k in [ks*32, ks*32+32)

    // ---- one-time weight loads into REGISTERS ----
    // phase A: 2 adjacent gate columns x 32 k (as k-pairs)
    ull wa0[16], wa1[16];
    const int q = lane >> 3, jp = lane & 7;
    const int clA = q * 16 + jp * 2;
    {
        const int gc = q * 256 + cb * 16 + jp * 2;
        const float* wp = whh + (size_t)(ks * 32) * G4 + gc;
#pragma unroll
        for (int i = 0; i < 16; i++) {
            float2 v0 = *(const float2*)(wp + (size_t)(2 * i) * G4);
            float2 v1 = *(const float2*)(wp + (size_t)(2 * i + 1) * G4);
            wa0[i] = f2pack(v0.x, v1.x);
            wa1[i] = f2pack(v0.y, v1.y);
        }
    }
    // phase B: 2 adjacent reparam columns x 32 k
    ull wb0[16], wb1[16];
    const int mm = lane >> 4, hf = (lane >> 3) & 1, jp2 = lane & 7;
    const int clB = mm * 32 + hf * 16 + jp2 * 2;
    {
        const float* M = mm ? crep : hrep;
        const int rc = hf * 256 + cb * 16 + jp2 * 2;
        const float* wp = M + (size_t)(ks * 32) * HS2 + rc;
#pragma unroll
        for (int i = 0; i < 16; i++) {
            float2 v0 = *(const float2*)(wp + (size_t)(2 * i) * HS2);
            float2 v1 = *(const float2*)(wp + (size_t)(2 * i + 1) * HS2);
            wb0[i] = f2pack(v0.x, v1.x);
            wb1[i] = f2pack(v0.y, v1.y);
        }
    }

    const float* srcA = g_h + (size_t)(rg * 8) * HSZ + ks * 32;
    const float* srcB = (mm ? g_preC : g_preH) + (size_t)(rg * 8) * HSZ + ks * 32;

    // nonlinearity mapping (tid < 128)
    const int nj = tid & 15, nr = (tid >> 4) & 7;
    // sampling mapping (all 256)
    const int smm = tid >> 7, srow = (tid >> 4) & 7, sjj = tid & 15;
    const int sb = rg * 8 + srow, sj = cb * 16 + sjj;
    const float* epsp = smm ? eps_c : eps_h;
    const size_t off_seq = smm ? OFF_CSEQ : OFF_HSEQ;
    const size_t off_mu  = smm ? OFF_CMU  : OFF_HMU;
    const size_t off_std = smm ? OFF_CSTD : OFF_HSTD;
    const size_t off_fin = smm ? OFF_CT   : OFF_HT;

    if (tid < 128) Cs[tid] = 0.f;
    __syncthreads();

    unsigned target = 0;

    for (int t = 0; t < TT; t++) {
        // ---- prefetch XW(t) + eps(t) ----
        float xw0 = 0.f, xw1 = 0.f, xw2 = 0.f, xw3 = 0.f;
        if (tid < 128) {
            const float* xp = g_XW + (size_t)(t * BB + rg * 8 + nr) * G4 + cb * 16 + nj;
            xw0 = __ldcg(xp);
            xw1 = __ldcg(xp + 256);
            xw2 = __ldcg(xp + 512);
            xw3 = __ldcg(xp + 768);
        }
        const float ep = __ldg(&epsp[((size_t)t * BB + sb) * HSZ + sj]);

        // ---- phase A: partial gates = h @ W_hh slice (all warps) ----
        {
            ull a0[8], a1[8];
#pragma unroll
            for (int r = 0; r < 8; r++) { a0[r] = 0ull; a1[r] = 0ull; }
            if (t) {
#pragma unroll
                for (int i = 0; i < 8; i++) {
                    ull hl[4], hh[4];
#pragma unroll
                    for (int r = 0; r < 4; r++) ld16cg(srcA + r * HSZ + i * 4, hl[r], hh[r]);
#pragma unroll
                    for (int r = 0; r < 4; r++) {
                        f2fma(a0[r], hl[r], wa0[2 * i]); f2fma(a0[r], hh[r], wa0[2 * i + 1]);
                        f2fma(a1[r], hl[r], wa1[2 * i]); f2fma(a1[r], hh[r], wa1[2 * i + 1]);
                    }
#pragma unroll
                    for (int r = 0; r < 4; r++) ld16cg(srcA + (r + 4) * HSZ + i * 4, hl[r], hh[r]);
#pragma unroll
                    for (int r = 0; r < 4; r++) {
                        f2fma(a0[r + 4], hl[r], wa0[2 * i]); f2fma(a0[r + 4], hh[r], wa0[2 * i + 1]);
                        f2fma(a1[r + 4], hl[r], wa1[2 * i]); f2fma(a1[r + 4], hh[r], wa1[2 * i + 1]);
                    }
                }
            }
#pragma unroll
            for (int r = 0; r < 8; r++) {
                *(float2*)&Part[(r * 8 + ks) * PP + clA] =
                    make_float2(f2sum(a0[r]), f2sum(a1[r]));
            }
        }
        __syncthreads();

        // ---- nonlinearity -> pre_c, pre_h ----
        if (tid < 128) {
            float s0 = 0.f, s1 = 0.f, s2 = 0.f, s3 = 0.f;
            const int b0 = nr * 8 * PP + nj;
#pragma unroll
            for (int k = 0; k < 8; k++) {
                s0 += Part[b0 + k * PP];
                s1 += Part[b0 + k * PP + 16];
                s2 += Part[b0 + k * PP + 32];
                s3 += Part[b0 + k * PP + 48];
            }
            float vi = fsig_(s0 + xw0);
            float vf = fsig_(s1 + xw1);
            float vg = ftanh_(s2 + xw2);
            float vo = fsig_(s3 + xw3);
            float cold = Cs[tid];
            float pc = vf * cold + vi * vg;
            float ph = vo * ftanh_(cold);
            int b = rg * 8 + nr, j = cb * 16 + nj;
            __stcg(&g_preC[b * HSZ + j], pc);
            __stcg(&g_preH[b * HSZ + j], ph);
        }
        if (use_cluster) {
            cl_barrier();
        } else {
            target += 16;
            rg_barrier(bar, target);
        }

        // ---- phase B: reparam partials (all warps) ----
        {
            ull a0[8], a1[8];
#pragma unroll
            for (int r = 0; r < 8; r++) { a0[r] = 0ull; a1[r] = 0ull; }
#pragma unroll
            for (int i = 0; i < 8; i++) {
                ull hl[4], hh[4];
#pragma unroll
                for (int r = 0; r < 4; r++) ld16cg(srcB + r * HSZ + i * 4, hl[r], hh[r]);
#pragma unroll
                for (int r = 0; r < 4; r++) {
                    f2fma(a0[r], hl[r], wb0[2 * i]); f2fma(a0[r], hh[r], wb0[2 * i + 1]);
                    f2fma(a1[r], hl[r], wb1[2 * i]); f2fma(a1[r], hh[r], wb1[2 * i + 1]);
                }
#pragma unroll
                for (int r = 0; r < 4; r++) ld16cg(srcB + (r + 4) * HSZ + i * 4, hl[r], hh[r]);
#pragma unroll
                for (int r = 0; r < 4; r++) {
                    f2fma(a0[r + 4], hl[r], wb0[2 * i]); f2fma(a0[r + 4], hh[r], wb0[2 * i + 1]);
                    f2fma(a1[r + 4], hl[r], wb1[2 * i]); f2fma(a1[r + 4], hh[r], wb1[2 * i + 1]);
                }
            }
#pragma unroll
            for (int r = 0; r < 8; r++) {
                *(float2*)&Part[(r * 8 + ks) * PP + clB] =
                    make_float2(f2sum(a0[r]), f2sum(a1[r]));
            }
        }
        __syncthreads();

        // ---- sample + write outputs + update state ----
        {
            const int b0 = srow * 8 * PP + smm * 32 + sjj;
            float mu = 0.f, sr = 0.f;
#pragma unroll
            for (int k = 0; k < 8; k++) {
                mu += Part[b0 + k * PP];
                sr += Part[b0 + k * PP + 16];
            }
            mu = fminf(fmaxf(mu, 1e-6f), 1e6f);
            float sp = fmaxf(sr, 0.f) + log1pf(__expf(-fabsf(sr)));
            float sd = fmaxf(sp, 1e-6f);
            float val = fmaf(ep, sd, mu);
            if (smm) Cs[srow * 16 + sjj] = val;            // c stays CTA-local
            else __stcg(&g_h[sb * HSZ + sj], val);         // h crosses CTAs
            size_t o = (size_t)sb * (TT * HSZ) + (size_t)t * HSZ + sj;
            out[off_seq + o] = val;
            out[off_mu + o] = mu;
            out[off_std + o] = sd;
            if (t == TT - 1) out[off_fin + sb * HSZ + sj] = val;
        }
        if (use_cluster) {
            cl_barrier();
        } else {
            target += 16;
            rg_barrier(bar, target);
        }
    }
}

// ---------------- launch ----------------
extern "C" void kernel_launch(void* const* d_in, const int* in_sizes, int n_in,
                              void* d_out, int out_size) {
    (void)in_sizes; (void)n_in; (void)out_size;
    const float* x     = (const float*)d_in[0];
    const float* wih   = (const float*)d_in[1];
    const float* whh   = (const float*)d_in[2];
    const float* bias  = (const float*)d_in[3];
    const float* hrep  = (const float*)d_in[4];
    const float* crep  = (const float*)d_in[5];
    const float* eps_h = (const float*)d_in[6];
    const float* eps_c = (const float*)d_in[7];
    float* out = (float*)d_out;

    bar_reset_kernel<<<1, 32>>>();
    xw_kernel<<<dim3(16, 8, 64), 256>>>(x, wih, bias);

    // Try 16-CTA clusters (nonportable size) for the rowgroup barriers.
    cudaFuncSetAttribute(lstm_kernel, cudaFuncAttributeNonPortableClusterSizeAllowed, 1);
    int maxc = 0;
    {
        cudaLaunchConfig_t q = {};
        q.gridDim = dim3(128);
        q.blockDim = dim3(256);
        cudaOccupancyMaxPotentialClusterSize(&maxc, (const void*)lstm_kernel, &q);
        cudaGetLastError();  // clear any non-sticky error from the query
    }
    if (maxc >= 16) {
        cudaLaunchConfig_t cfg = {};
        cfg.gridDim = dim3(128);
        cfg.blockDim = dim3(256);
        cudaLaunchAttribute attrs[1];
        attrs[0].id = cudaLaunchAttributeClusterDimension;
        attrs[0].val.clusterDim.x = 16;
        attrs[0].val.clusterDim.y = 1;
        attrs[0].val.clusterDim.z = 1;
        cfg.attrs = attrs;
        cfg.numAttrs = 1;
        cudaError_t e = cudaLaunchKernelEx(&cfg, lstm_kernel,
                                           whh, hrep, crep, eps_h, eps_c, out, 1);
        if (e == cudaSuccess) return;
        cudaGetLastError();
    }
    // Fallback: global-memory barrier path
    lstm_kernel<<<128, 256>>>(whh, hrep, crep, eps_h, eps_c, out, 0);
}

// round 12
// speedup vs baseline: 1.3942x; 1.3942x over previous
#include <cuda_runtime.h>
#include <math.h>
#include <stdint.h>

#define BB 64
#define TT 512
#define DD 256
#define HSZ 256
#define G4 1024
#define HS2 512

typedef unsigned long long ull;

// ---------------- device scratch (static: no allocation) ----------------
__device__ float g_XW[(size_t)TT * BB * G4];  // [t][b][gatecol]  128MB
__device__ float g_preH[BB * HSZ];
__device__ float g_preC[BB * HSZ];
__device__ float g_h[BB * HSZ];
__device__ unsigned g_bar[8];

// output offsets (floats)
#define OFF_HSEQ ((size_t)0)
#define OFF_CSEQ ((size_t)8388608)
#define OFF_HMU  ((size_t)16777216)
#define OFF_HSTD ((size_t)25165824)
#define OFF_CMU  ((size_t)33554432)
#define OFF_CSTD ((size_t)41943040)
#define OFF_HT   ((size_t)50331648)
#define OFF_CT   ((size_t)50348032)

// ---------------- f32x2 helpers ----------------
__device__ __forceinline__ void f2fma(ull& d, ull a, ull b) {
    asm("fma.rn.f32x2 %0, %1, %2, %0;" : "+l"(d) : "l"(a), "l"(b));
}
__device__ __forceinline__ float f2sum(ull v) {
    float lo, hi;
    asm("mov.b64 {%0,%1}, %2;" : "=f"(lo), "=f"(hi) : "l"(v));
    return lo + hi;
}
__device__ __forceinline__ ull f2pack(float lo, float hi) {
    ull v;
    asm("mov.b64 %0, {%1,%2};" : "=l"(v) : "f"(lo), "f"(hi));
    return v;
}

__global__ void bar_reset_kernel() {
    if (threadIdx.x < 8) g_bar[threadIdx.x] = 0u;
}

// ---------------- precompute: XW[t][b][col] = x[b][t][:] @ W_ih + bias ----------------
#define XSP_STRIDE 140
#define WSP_STRIDE 132

__global__ __launch_bounds__(256) void xw_kernel(const float* __restrict__ x,
                                                 const float* __restrict__ wih,
                                                 const float* __restrict__ bias) {
    __shared__ float XsP[32 * XSP_STRIDE];  // [k2][t*2+par]
    __shared__ float WsP[32 * WSP_STRIDE];  // [k2][col*2+par]
    const int bx = blockIdx.x;      // 0..15  col block (64 cols)
    const int by = blockIdx.y;      // 0..7   t block (64 t)
    const int bz = blockIdx.z;      // 0..63  b
    const int tid = threadIdx.x;
    const int tx = tid & 15;        // col quad
    const int ty = tid >> 4;        // t quad

    ull acc[4][4];
#pragma unroll
    for (int i = 0; i < 4; i++)
#pragma unroll
        for (int j = 0; j < 4; j++) acc[i][j] = 0ull;

    for (int kc = 0; kc < 4; kc++) {
        const int k0 = kc * 64;
        __syncthreads();
        for (int i = tid; i < 4096; i += 256) {
            int kk = i >> 6, cc = i & 63;
            WsP[(kk >> 1) * WSP_STRIDE + cc * 2 + (kk & 1)] =
                wih[(size_t)(k0 + kk) * G4 + bx * 64 + cc];
        }
        for (int i = tid; i < 4096; i += 256) {
            int tt2 = i >> 6, kk = i & 63;
            XsP[(kk >> 1) * XSP_STRIDE + tt2 * 2 + (kk & 1)] =
                x[((size_t)bz * TT + by * 64 + tt2) * DD + k0 + kk];
        }
        __syncthreads();
#pragma unroll 8
        for (int kk2 = 0; kk2 < 32; kk2++) {
            const float* XP = &XsP[kk2 * XSP_STRIDE + ty * 8];
            const float* WP = &WsP[kk2 * WSP_STRIDE + tx * 8];
            ulonglong2 aA = *(const ulonglong2*)XP;
            ulonglong2 aB = *(const ulonglong2*)(XP + 4);
            ulonglong2 wA = *(const ulonglong2*)WP;
            ulonglong2 wB = *(const ulonglong2*)(WP + 4);
            f2fma(acc[0][0], aA.x, wA.x); f2fma(acc[0][1], aA.x, wA.y);
            f2fma(acc[0][2], aA.x, wB.x); f2fma(acc[0][3], aA.x, wB.y);
            f2fma(acc[1][0], aA.y, wA.x); f2fma(acc[1][1], aA.y, wA.y);
            f2fma(acc[1][2], aA.y, wB.x); f2fma(acc[1][3], aA.y, wB.y);
            f2fma(acc[2][0], aB.x, wA.x); f2fma(acc[2][1], aB.x, wA.y);
            f2fma(acc[2][2], aB.x, wB.x); f2fma(acc[2][3], aB.x, wB.y);
            f2fma(acc[3][0], aB.y, wA.x); f2fma(acc[3][1], aB.y, wA.y);
            f2fma(acc[3][2], aB.y, wB.x); f2fma(acc[3][3], aB.y, wB.y);
        }
    }
    const int col0 = bx * 64 + tx * 4;
    const float4 bv = *(const float4*)&bias[col0];
#pragma unroll
    for (int i = 0; i < 4; i++) {
        int t = by * 64 + ty * 4 + i;
        float4 v;
        v.x = f2sum(acc[i][0]) + bv.x;
        v.y = f2sum(acc[i][1]) + bv.y;
        v.z = f2sum(acc[i][2]) + bv.z;
        v.w = f2sum(acc[i][3]) + bv.w;
        *(float4*)&g_XW[((size_t)t * BB + bz) * G4 + col0] = v;
    }
}

// ---------------- fast nonlinearities ----------------
__device__ __forceinline__ float ftanh_(float x) {
    float e = __expf(-2.f * fabsf(x));
    float t = __fdividef(1.f - e, 1.f + e);
    return copysignf(t, x);
}
__device__ __forceinline__ float fsig_(float x) {
    return fmaf(0.5f, ftanh_(0.5f * x), 0.5f);
}

__device__ __forceinline__ void rg_barrier(unsigned* bar, unsigned target) {
    __syncthreads();
    if (threadIdx.x == 0) {
        asm volatile("red.release.gpu.add.u32 [%0], 1;" :: "l"(bar) : "memory");
        unsigned v;
        do {
            asm volatile("ld.acquire.gpu.u32 %0, [%1];" : "=r"(v) : "l"(bar) : "memory");
        } while (v < target);
    }
    __syncthreads();
}

// ---------------- persistent recurrent kernel (register weights + SMEM-staged acts) ----------------
#define PAD 68
#define HP 264   // activation row pitch (floats), float4-aligned

__global__ __launch_bounds__(256, 1) void lstm_kernel(const float* __restrict__ whh,
                                                      const float* __restrict__ hrep,
                                                      const float* __restrict__ crep,
                                                      const float* __restrict__ eps_h,
                                                      const float* __restrict__ eps_c,
                                                      float* __restrict__ out) {
    __shared__ __align__(16) float Part[8 * 4 * PAD];  // [r][ks][cl] padded
    __shared__ float Cs[128];                          // c state, CTA-local [r*16+j]
    __shared__ __align__(16) float Ha[8 * HP];         // staged h rows [r][k]
    __shared__ __align__(16) float PB[2 * 8 * HP];     // staged preH/preC [m][r][k]

    const int tid = threadIdx.x;
    const int rg = blockIdx.x >> 4;       // row group: rows rg*8 .. rg*8+7
    const int cb = blockIdx.x & 15;       // col block
    unsigned* bar = &g_bar[rg];
    const int w = tid >> 5, lane = tid & 31;
    const bool roleA = (w < 4);
    const int ks = roleA ? w : (w - 4);   // k-slice: k in [ks*64, ks*64+64)

    // ---- one-time weight load into REGISTERS (2 cols x 64 k, as k-pairs) ----
    ull wc0[32], wc1[32];
    int cl0;  // local output column base (even)
    if (roleA) {
        const int q = lane >> 3, jp = lane & 7;
        const int gc = q * 256 + cb * 16 + jp * 2;
        const float* wp = whh + (size_t)(ks * 64) * G4 + gc;
        cl0 = q * 16 + jp * 2;
#pragma unroll
        for (int i = 0; i < 32; i++) {
            float2 v0 = *(const float2*)(wp + (size_t)(2 * i) * G4);
            float2 v1 = *(const float2*)(wp + (size_t)(2 * i + 1) * G4);
            wc0[i] = f2pack(v0.x, v1.x);
            wc1[i] = f2pack(v0.y, v1.y);
        }
    } else {
        const int mm = lane >> 4, hf = (lane >> 3) & 1, jp = lane & 7;
        const float* M = mm ? crep : hrep;
        const int rc = hf * 256 + cb * 16 + jp * 2;
        const float* wp = M + (size_t)(ks * 64) * HS2 + rc;
        cl0 = mm * 32 + hf * 16 + jp * 2;
#pragma unroll
        for (int i = 0; i < 32; i++) {
            float2 v0 = *(const float2*)(wp + (size_t)(2 * i) * HS2);
            float2 v1 = *(const float2*)(wp + (size_t)(2 * i + 1) * HS2);
            wc0[i] = f2pack(v0.x, v1.x);
            wc1[i] = f2pack(v0.y, v1.y);
        }
    }

    // phase operand bases in SMEM (warp-uniform addresses -> LDS broadcast)
    const float* srcA = &Ha[ks * 64];
    const float* srcB = &PB[(size_t)(roleA ? 0 : (lane >> 4)) * 8 * HP + ks * 64];

    // nonlinearity mapping (tid < 128)
    const int nj = tid & 15, nr = (tid >> 4) & 7;
    // sampling mapping (all 256)
    const int smm = tid >> 7, srow = (tid >> 4) & 7, sjj = tid & 15;
    const int sb = rg * 8 + srow, sj = cb * 16 + sjj;
    const float* epsp = smm ? eps_c : eps_h;
    const size_t off_seq = smm ? OFF_CSEQ : OFF_HSEQ;
    const size_t off_mu  = smm ? OFF_CMU  : OFF_HMU;
    const size_t off_std = smm ? OFF_CSTD : OFF_HSTD;
    const size_t off_fin = smm ? OFF_CT   : OFF_HT;

    if (tid < 128) Cs[tid] = 0.f;
    __syncthreads();

    unsigned target = 0;

    for (int t = 0; t < TT; t++) {
        // ---- prefetch XW(t) + eps(t) ----
        float xw0 = 0.f, xw1 = 0.f, xw2 = 0.f, xw3 = 0.f;
        if (tid < 128) {
            const float* xp = g_XW + (size_t)(t * BB + rg * 8 + nr) * G4 + cb * 16 + nj;
            xw0 = __ldcg(xp);
            xw1 = __ldcg(xp + 256);
            xw2 = __ldcg(xp + 512);
            xw3 = __ldcg(xp + 768);
        }
        const float ep = __ldg(&epsp[((size_t)t * BB + sb) * HSZ + sj]);

        // ---- stage h rows into SMEM ----
        if (t == 0) {
            float4 z = make_float4(0.f, 0.f, 0.f, 0.f);
            for (int i = tid; i < 512; i += 256) {
                *(float4*)&Ha[(i >> 6) * HP + ((i & 63) << 2)] = z;
            }
        } else {
            for (int i = tid; i < 512; i += 256) {
                int r = i >> 6, k4 = (i & 63) << 2;
                *(float4*)&Ha[r * HP + k4] =
                    __ldcg((const float4*)&g_h[(rg * 8 + r) * HSZ + k4]);
            }
        }
        __syncthreads();

        // ---- phase A: partial gates = h @ W_hh slice (warps 0-3, LDS broadcast) ----
        if (roleA) {
            ull a0[8], a1[8];
#pragma unroll
            for (int r = 0; r < 8; r++) { a0[r] = 0ull; a1[r] = 0ull; }
#pragma unroll 4
            for (int i = 0; i < 16; i++) {
                ull hl[8], hh[8];
#pragma unroll
                for (int r = 0; r < 8; r++) {
                    ulonglong2 v = *(const ulonglong2*)&srcA[r * HP + i * 4];
                    hl[r] = v.x; hh[r] = v.y;
                }
#pragma unroll
                for (int r = 0; r < 8; r++) {
                    f2fma(a0[r], hl[r], wc0[2 * i]); f2fma(a0[r], hh[r], wc0[2 * i + 1]);
                    f2fma(a1[r], hl[r], wc1[2 * i]); f2fma(a1[r], hh[r], wc1[2 * i + 1]);
                }
            }
#pragma unroll
            for (int r = 0; r < 8; r++) {
                *(float2*)&Part[(r * 4 + ks) * PAD + cl0] =
                    make_float2(f2sum(a0[r]), f2sum(a1[r]));
            }
        }
        __syncthreads();

        // ---- nonlinearity -> pre_c, pre_h (exchange via L2) ----
        if (tid < 128) {
            float s0, s1, s2, s3;
            {
                int b0 = nr * 4 * PAD + nj;
                s0 = Part[b0] + Part[b0 + PAD] + Part[b0 + 2 * PAD] + Part[b0 + 3 * PAD];
                s1 = Part[b0 + 16] + Part[b0 + 16 + PAD] + Part[b0 + 16 + 2 * PAD] + Part[b0 + 16 + 3 * PAD];
                s2 = Part[b0 + 32] + Part[b0 + 32 + PAD] + Part[b0 + 32 + 2 * PAD] + Part[b0 + 32 + 3 * PAD];
                s3 = Part[b0 + 48] + Part[b0 + 48 + PAD] + Part[b0 + 48 + 2 * PAD] + Part[b0 + 48 + 3 * PAD];
            }
            float vi = fsig_(s0 + xw0);
            float vf = fsig_(s1 + xw1);
            float vg = ftanh_(s2 + xw2);
            float vo = fsig_(s3 + xw3);
            float cold = Cs[tid];
            float pc = vf * cold + vi * vg;
            float ph = vo * ftanh_(cold);
            int b = rg * 8 + nr, j = cb * 16 + nj;
            __stcg(&g_preC[b * HSZ + j], pc);
            __stcg(&g_preH[b * HSZ + j], ph);
        }
        target += 16;
        rg_barrier(bar, target);

        // ---- stage preH/preC rows into SMEM ----
        for (int i = tid; i < 1024; i += 256) {
            int m = i >> 9, r = (i >> 6) & 7, k4 = (i & 63) << 2;
            const float* src = m ? g_preC : g_preH;
            *(float4*)&PB[(m * 8 + r) * HP + k4] =
                __ldcg((const float4*)&src[(rg * 8 + r) * HSZ + k4]);
        }
        __syncthreads();

        // ---- phase B: reparam partials (warps 4-7, LDS broadcast) ----
        if (!roleA) {
            ull a0[8], a1[8];
#pragma unroll
            for (int r = 0; r < 8; r++) { a0[r] = 0ull; a1[r] = 0ull; }
#pragma unroll 4
            for (int i = 0; i < 16; i++) {
                ull hl[8], hh[8];
#pragma unroll
                for (int r = 0; r < 8; r++) {
                    ulonglong2 v = *(const ulonglong2*)&srcB[r * HP + i * 4];
                    hl[r] = v.x; hh[r] = v.y;
                }
#pragma unroll
                for (int r = 0; r < 8; r++) {
                    f2fma(a0[r], hl[r], wc0[2 * i]); f2fma(a0[r], hh[r], wc0[2 * i + 1]);
                    f2fma(a1[r], hl[r], wc1[2 * i]); f2fma(a1[r], hh[r], wc1[2 * i + 1]);
                }
            }
#pragma unroll
            for (int r = 0; r < 8; r++) {
                *(float2*)&Part[(r * 4 + ks) * PAD + cl0] =
                    make_float2(f2sum(a0[r]), f2sum(a1[r]));
            }
        }
        __syncthreads();

        // ---- sample + write outputs + update state ----
        {
            int b0 = srow * 4 * PAD + smm * 32 + sjj;
            float mu = Part[b0] + Part[b0 + PAD] + Part[b0 + 2 * PAD] + Part[b0 + 3 * PAD];
            float sr = Part[b0 + 16] + Part[b0 + 16 + PAD] + Part[b0 + 16 + 2 * PAD] + Part[b0 + 16 + 3 * PAD];
            mu = fminf(fmaxf(mu, 1e-6f), 1e6f);
            float sp = fmaxf(sr, 0.f) + log1pf(__expf(-fabsf(sr)));
            float sd = fmaxf(sp, 1e-6f);
            float val = fmaf(ep, sd, mu);
            if (smm) Cs[srow * 16 + sjj] = val;            // c stays CTA-local
            else __stcg(&g_h[sb * HSZ + sj], val);         // h crosses CTAs
            size_t o = (size_t)sb * (TT * HSZ) + (size_t)t * HSZ + sj;
            out[off_seq + o] = val;
            out[off_mu + o] = mu;
            out[off_std + o] = sd;
            if (t == TT - 1) out[off_fin + sb * HSZ + sj] = val;
        }
        target += 16;
        rg_barrier(bar, target);
    }
}

// ---------------- launch ----------------
extern "C" void kernel_launch(void* const* d_in, const int* in_sizes, int n_in,
                              void* d_out, int out_size) {
    (void)in_sizes; (void)n_in; (void)out_size;
    const float* x     = (const float*)d_in[0];
    const float* wih   = (const float*)d_in[1];
    const float* whh   = (const float*)d_in[2];
    const float* bias  = (const float*)d_in[3];
    const float* hrep  = (const float*)d_in[4];
    const float* crep  = (const float*)d_in[5];
    const float* eps_h = (const float*)d_in[6];
    const float* eps_c = (const float*)d_in[7];
    float* out = (float*)d_out;

    bar_reset_kernel<<<1, 32>>>();
    xw_kernel<<<dim3(16, 8, 64), 256>>>(x, wih, bias);
    lstm_kernel<<<128, 256>>>(whh, hrep, crep, eps_h, eps_c, out);
}